// round 11
// baseline (speedup 1.0000x reference)
#include <cuda_runtime.h>
#include <stdint.h>

#define ROW_N 2048
#define K_SEL 1024
#define NT    256
#define CAP   80
#define FULLM 0xFFFFFFFFu

__device__ __forceinline__ uint32_t f2u_ord(float x) {
    uint32_t b = __float_as_uint(x);
    uint32_t m = (uint32_t)(((int32_t)b) >> 31) | 0x80000000u;
    return b ^ m;
}
__device__ __forceinline__ float u2f_ord(uint32_t u) {
    uint32_t m = (uint32_t)(((int32_t)(~u)) >> 31) | 0x80000000u;
    return __uint_as_float(u ^ m);
}

__global__ __launch_bounds__(NT, 8) void kta_kernel(const float* __restrict__ in,
                                                    float* __restrict__ out) {
    __shared__ uint32_t s_hist[512];          // two 256-bin histograms (2 KB)
    __shared__ float    s_cand[2][CAP];       // small gather buffers (640 B)
    __shared__ uint32_t s_w[2][8];
    __shared__ uint32_t s_selbin[2], s_selrem[2];
    __shared__ uint32_t s_cnt[2];
    __shared__ float    s_T[2];
    __shared__ uint32_t s_minu, s_c;          // overflow fallback scratch

    const int t    = threadIdx.x;
    const int lane = t & 31;
    const int wid  = t >> 5;
    const size_t baseA = (size_t)blockIdx.x * (2 * ROW_N);
    const float4* inA  = (const float4*)(in  + baseA);
    const float4* inB  = (const float4*)(in  + baseA + ROW_N);
    float4*       outA = (float4*)(out + baseA);
    float4*       outB = (float4*)(out + baseA + ROW_N);

    // ---- load both rows: 4 consecutive LDG.128 ----
    float4 a0 = inA[t], a1 = inA[t + NT], b0 = inB[t], b1 = inB[t + NT];
    float fa[8] = {a0.x,a0.y,a0.z,a0.w, a1.x,a1.y,a1.z,a1.w};
    float fb[8] = {b0.x,b0.y,b0.z,b0.w, b1.x,b1.y,b1.z,b1.w};

    bool gotA = false, gotB = false;
    int  lvlA = 0, lvlB = 0;

    for (int lvl = 0; lvl < 3; lvl++) {
        const float scale = (lvl == 0) ? 1280.0f : (256.0f / 1.2f);

        s_hist[t] = 0; s_hist[t + 256] = 0;
        if (t == 0) {
            if (!gotA) s_selbin[0] = FULLM;
            if (!gotB) s_selbin[1] = FULLM;
            s_cnt[0] = 0; s_cnt[1] = 0;
        }
        __syncthreads();

        // ---- fused histogram + count-below, both rows ----
        if (!gotA) {
            uint32_t clo = 0;
#pragma unroll
            for (int e = 0; e < 8; e++) {
                int b = (lvl < 2) ? __float2int_rd(fmaf(fa[e], scale, 128.0f))
                                  : (int)(f2u_ord(fa[e]) >> 24);
                clo += ((uint32_t)b >> 31);
                if ((unsigned)b < 256u) atomicAdd(&s_hist[b], 1u);
            }
            clo = __reduce_add_sync(FULLM, clo);
            if (lane == 0) s_w[0][wid] = clo;
        }
        if (!gotB) {
            uint32_t clo = 0;
#pragma unroll
            for (int e = 0; e < 8; e++) {
                int b = (lvl < 2) ? __float2int_rd(fmaf(fb[e], scale, 128.0f))
                                  : (int)(f2u_ord(fb[e]) >> 24);
                clo += ((uint32_t)b >> 31);
                if ((unsigned)b < 256u) atomicAdd(&s_hist[256 + b], 1u);
            }
            clo = __reduce_add_sync(FULLM, clo);
            if (lane == 0) s_w[1][wid] = clo;
        }
        __syncthreads();

        // ---- warps 0/1 scan their row's bins ----
        if (wid < 2) {
            const int r = wid;
            const bool need = (r == 0) ? !gotA : !gotB;
            if (need) {
                uint32_t x = (lane < 8) ? s_w[r][lane] : 0u;
                const int clo = (int)__reduce_add_sync(FULLM, x);
                const int k2  = K_SEL - clo;

                const uint4* h4 = (const uint4*)(s_hist + r * 256);
                uint4 p = h4[lane * 2], q = h4[lane * 2 + 1];
                uint32_t c[8] = {p.x,p.y,p.z,p.w, q.x,q.y,q.z,q.w};
                uint32_t lt = c[0]+c[1]+c[2]+c[3]+c[4]+c[5]+c[6]+c[7];
                uint32_t inc = lt;
#pragma unroll
                for (int o = 1; o < 32; o <<= 1) {
                    uint32_t v = __shfl_up_sync(FULLM, inc, o);
                    if (lane >= o) inc += v;
                }
                int exc = (int)(inc - lt);
                if (exc < k2 && k2 <= (int)inc) {
                    int run = exc, fbn = -1;
#pragma unroll
                    for (int j = 0; j < 8; j++) {
                        if (fbn < 0 && run < k2 && k2 <= run + (int)c[j]) fbn = j;
                        else if (fbn < 0) run += (int)c[j];
                    }
                    s_selbin[r] = (uint32_t)(lane * 8 + fbn);
                    s_selrem[r] = (uint32_t)(k2 - run);
                }
            }
        }
        __syncthreads();

        bool pA = gotA, pB = gotB;
        gotA = (s_selbin[0] != FULLM);
        gotB = (s_selbin[1] != FULLM);
        if (!pA && gotA) lvlA = lvl;
        if (!pB && gotB) lvlB = lvl;
        if (gotA && gotB) break;
    }

    const int bselA = (int)s_selbin[0], bselB = (int)s_selbin[1];
    const float scA = (lvlA == 0) ? 1280.0f : (256.0f / 1.2f);
    const float scB = (lvlB == 0) ? 1280.0f : (256.0f / 1.2f);

    // ---- gather crossing-bin elements (capped; bit-identical bin math) ----
#pragma unroll
    for (int e = 0; e < 8; e++) {
        int b = (lvlA < 2) ? __float2int_rd(fmaf(fa[e], scA, 128.0f))
                           : (int)(f2u_ord(fa[e]) >> 24);
        if (b == bselA) {
            uint32_t pos = atomicAdd(&s_cnt[0], 1u);
            if (pos < CAP) s_cand[0][pos] = fa[e];
        }
    }
#pragma unroll
    for (int e = 0; e < 8; e++) {
        int b = (lvlB < 2) ? __float2int_rd(fmaf(fb[e], scB, 128.0f))
                           : (int)(f2u_ord(fb[e]) >> 24);
        if (b == bselB) {
            uint32_t pos = atomicAdd(&s_cnt[1], 1u);
            if (pos < CAP) s_cand[1][pos] = fb[e];
        }
    }
    __syncthreads();

    // ---- per-row threshold ----
#pragma unroll
    for (int r = 0; r < 2; r++) {
        const int   B    = (int)s_cnt[r];
        int         rem  = (int)s_selrem[r];
        const int   bsel = (r == 0) ? bselA : bselB;
        const int   lvlR = (r == 0) ? lvlA  : lvlB;
        const float scR  = (r == 0) ? scA   : scB;
        const float* fr  = (r == 0) ? fa    : fb;

        if (B <= CAP) {
            // happy path: exact rank among B captured values
            if (t < B) {
                float v = s_cand[r][t];
                int less = 0, leq = 0;
                for (int j = 0; j < B; j++) {
                    float c = s_cand[r][j];
                    less += (c <  v) ? 1 : 0;
                    leq  += (c <= v) ? 1 : 0;
                }
                if (less < rem && rem <= leq) s_T[r] = v;
            }
        } else {
            // rare overflow: buffer-free min-extraction on register values
            uint32_t curnext = 0;
            while (true) {
                if (t == 0) { s_minu = FULLM; s_c = 0; }
                __syncthreads();
#pragma unroll
                for (int e = 0; e < 8; e++) {
                    int b = (lvlR < 2) ? __float2int_rd(fmaf(fr[e], scR, 128.0f))
                                       : (int)(f2u_ord(fr[e]) >> 24);
                    uint32_t u = f2u_ord(fr[e]);
                    if (b == bsel && u >= curnext) atomicMin(&s_minu, u);
                }
                __syncthreads();
                uint32_t m = s_minu;
                if (m == FULLM) { if (t == 0) s_T[r] = u2f_ord(curnext - 1u); __syncthreads(); break; }
#pragma unroll
                for (int e = 0; e < 8; e++)
                    if (f2u_ord(fr[e]) == m) atomicAdd(&s_c, 1u);
                __syncthreads();
                uint32_t dup = s_c;
                if ((int)dup >= rem) { if (t == 0) s_T[r] = u2f_ord(m); __syncthreads(); break; }
                rem    -= (int)dup;
                curnext = m + 1u;
                __syncthreads();
            }
        }
    }
    __syncthreads();
    const float TA = s_T[0], TB = s_T[1];

    // ---- output both rows from registers ----
    float4 oa0, oa1, ob0, ob1;
    oa0.x = (fa[0] <= TA) ? 0.0f : fa[0];
    oa0.y = (fa[1] <= TA) ? 0.0f : fa[1];
    oa0.z = (fa[2] <= TA) ? 0.0f : fa[2];
    oa0.w = (fa[3] <= TA) ? 0.0f : fa[3];
    oa1.x = (fa[4] <= TA) ? 0.0f : fa[4];
    oa1.y = (fa[5] <= TA) ? 0.0f : fa[5];
    oa1.z = (fa[6] <= TA) ? 0.0f : fa[6];
    oa1.w = (fa[7] <= TA) ? 0.0f : fa[7];
    ob0.x = (fb[0] <= TB) ? 0.0f : fb[0];
    ob0.y = (fb[1] <= TB) ? 0.0f : fb[1];
    ob0.z = (fb[2] <= TB) ? 0.0f : fb[2];
    ob0.w = (fb[3] <= TB) ? 0.0f : fb[3];
    ob1.x = (fb[4] <= TB) ? 0.0f : fb[4];
    ob1.y = (fb[5] <= TB) ? 0.0f : fb[5];
    ob1.z = (fb[6] <= TB) ? 0.0f : fb[6];
    ob1.w = (fb[7] <= TB) ? 0.0f : fb[7];
    outA[t]      = oa0;
    outA[t + NT] = oa1;
    outB[t]      = ob0;
    outB[t + NT] = ob1;
}

extern "C" void kernel_launch(void* const* d_in, const int* in_sizes, int n_in,
                              void* d_out, int out_size) {
    const float* in = (const float*)d_in[0];
    float* out = (float*)d_out;
    int pairs = in_sizes[0] / (2 * ROW_N);   // 16384
    kta_kernel<<<pairs, NT>>>(in, out);
}

// round 12
// speedup vs baseline: 1.0009x; 1.0009x over previous
#include <cuda_runtime.h>
#include <stdint.h>

#define ROW_N 2048
#define K_SEL 1024
#define NT    256
#define CAP   80
#define FULLM 0xFFFFFFFFu

__device__ __forceinline__ uint32_t f2u_ord(float x) {
    uint32_t b = __float_as_uint(x);
    uint32_t m = (uint32_t)(((int32_t)b) >> 31) | 0x80000000u;
    return b ^ m;
}
__device__ __forceinline__ float u2f_ord(uint32_t u) {
    uint32_t m = (uint32_t)(((int32_t)(~u)) >> 31) | 0x80000000u;
    return __uint_as_float(u ^ m);
}

__global__ __launch_bounds__(NT, 8) void kta_kernel(const float* __restrict__ in,
                                                    float* __restrict__ out) {
    __shared__ uint32_t s_hist[512];
    __shared__ float    s_cand[2][CAP];
    __shared__ uint32_t s_w[2][8];
    __shared__ uint32_t s_selbin[2], s_selrem[2];
    __shared__ uint32_t s_cnt[2];
    __shared__ float    s_T[2];
    __shared__ uint32_t s_minu, s_c;

    const int t    = threadIdx.x;
    const int lane = t & 31;
    const int wid  = t >> 5;
    const size_t baseA = (size_t)blockIdx.x * (2 * ROW_N);
    const float4* inA  = (const float4*)(in  + baseA);
    const float4* inB  = (const float4*)(in  + baseA + ROW_N);
    float4*       outA = (float4*)(out + baseA);
    float4*       outB = (float4*)(out + baseA + ROW_N);

    // ---- load both rows: 4 consecutive LDG.128 ----
    float4 a0 = inA[t], a1 = inA[t + NT], b0 = inB[t], b1 = inB[t + NT];
    float fa[8] = {a0.x,a0.y,a0.z,a0.w, a1.x,a1.y,a1.z,a1.w};
    float fb[8] = {b0.x,b0.y,b0.z,b0.w, b1.x,b1.y,b1.z,b1.w};

    bool gotA = false, gotB = false;
    int  lvlA = 0, lvlB = 0;

    for (int lvl = 0; lvl < 3; lvl++) {
        const float scale = (lvl == 0) ? 1280.0f : (256.0f / 1.2f);

        s_hist[t] = 0; s_hist[t + 256] = 0;
        if (t == 0) {
            if (!gotA) s_selbin[0] = FULLM;
            if (!gotB) s_selbin[1] = FULLM;
            s_cnt[0] = 0; s_cnt[1] = 0;
        }
        __syncthreads();

        if (!gotA) {
            uint32_t clo = 0;
#pragma unroll
            for (int e = 0; e < 8; e++) {
                int b = (lvl < 2) ? __float2int_rd(fmaf(fa[e], scale, 128.0f))
                                  : (int)(f2u_ord(fa[e]) >> 24);
                clo += ((uint32_t)b >> 31);
                if ((unsigned)b < 256u) atomicAdd(&s_hist[b], 1u);
            }
            clo = __reduce_add_sync(FULLM, clo);
            if (lane == 0) s_w[0][wid] = clo;
        }
        if (!gotB) {
            uint32_t clo = 0;
#pragma unroll
            for (int e = 0; e < 8; e++) {
                int b = (lvl < 2) ? __float2int_rd(fmaf(fb[e], scale, 128.0f))
                                  : (int)(f2u_ord(fb[e]) >> 24);
                clo += ((uint32_t)b >> 31);
                if ((unsigned)b < 256u) atomicAdd(&s_hist[256 + b], 1u);
            }
            clo = __reduce_add_sync(FULLM, clo);
            if (lane == 0) s_w[1][wid] = clo;
        }
        __syncthreads();

        if (wid < 2) {
            const int r = wid;
            const bool need = (r == 0) ? !gotA : !gotB;
            if (need) {
                uint32_t x = (lane < 8) ? s_w[r][lane] : 0u;
                const int clo = (int)__reduce_add_sync(FULLM, x);
                const int k2  = K_SEL - clo;

                const uint4* h4 = (const uint4*)(s_hist + r * 256);
                uint4 p = h4[lane * 2], q = h4[lane * 2 + 1];
                uint32_t c[8] = {p.x,p.y,p.z,p.w, q.x,q.y,q.z,q.w};
                uint32_t lt = c[0]+c[1]+c[2]+c[3]+c[4]+c[5]+c[6]+c[7];
                uint32_t inc = lt;
#pragma unroll
                for (int o = 1; o < 32; o <<= 1) {
                    uint32_t v = __shfl_up_sync(FULLM, inc, o);
                    if (lane >= o) inc += v;
                }
                int exc = (int)(inc - lt);
                if (exc < k2 && k2 <= (int)inc) {
                    int run = exc, fbn = -1;
#pragma unroll
                    for (int j = 0; j < 8; j++) {
                        if (fbn < 0 && run < k2 && k2 <= run + (int)c[j]) fbn = j;
                        else if (fbn < 0) run += (int)c[j];
                    }
                    s_selbin[r] = (uint32_t)(lane * 8 + fbn);
                    s_selrem[r] = (uint32_t)(k2 - run);
                }
            }
        }
        __syncthreads();

        bool pA = gotA, pB = gotB;
        gotA = (s_selbin[0] != FULLM);
        gotB = (s_selbin[1] != FULLM);
        if (!pA && gotA) lvlA = lvl;
        if (!pB && gotB) lvlB = lvl;
        if (gotA && gotB) break;
    }

    const int bselA = (int)s_selbin[0], bselB = (int)s_selbin[1];
    const float scA = (lvlA == 0) ? 1280.0f : (256.0f / 1.2f);
    const float scB = (lvlB == 0) ? 1280.0f : (256.0f / 1.2f);

    // ---- gather crossing-bin elements (direct register access only) ----
#pragma unroll
    for (int e = 0; e < 8; e++) {
        int b = (lvlA < 2) ? __float2int_rd(fmaf(fa[e], scA, 128.0f))
                           : (int)(f2u_ord(fa[e]) >> 24);
        if (b == bselA) {
            uint32_t pos = atomicAdd(&s_cnt[0], 1u);
            if (pos < CAP) s_cand[0][pos] = fa[e];
        }
    }
#pragma unroll
    for (int e = 0; e < 8; e++) {
        int b = (lvlB < 2) ? __float2int_rd(fmaf(fb[e], scB, 128.0f))
                           : (int)(f2u_ord(fb[e]) >> 24);
        if (b == bselB) {
            uint32_t pos = atomicAdd(&s_cnt[1], 1u);
            if (pos < CAP) s_cand[1][pos] = fb[e];
        }
    }
    __syncthreads();

    // ---- per-row threshold; NO dynamic indexing of register arrays ----
#define ROW_THRESH(R, FARR, LVLR, SCR, BSELR)                                       \
    {                                                                               \
        const int B   = (int)s_cnt[R];                                              \
        int       rem = (int)s_selrem[R];                                           \
        if (B <= CAP) {                                                             \
            if (t < B) {                                                            \
                float v = s_cand[R][t];                                             \
                int less = 0, leq = 0;                                              \
                for (int j = 0; j < B; j++) {                                       \
                    float c = s_cand[R][j];                                         \
                    less += (c <  v) ? 1 : 0;                                       \
                    leq  += (c <= v) ? 1 : 0;                                       \
                }                                                                   \
                if (less < rem && rem <= leq) s_T[R] = v;                           \
            }                                                                       \
        } else {                                                                    \
            uint32_t curnext = 0;                                                   \
            while (true) {                                                          \
                if (t == 0) { s_minu = FULLM; s_c = 0; }                            \
                __syncthreads();                                                    \
                _Pragma("unroll")                                                   \
                for (int e = 0; e < 8; e++) {                                       \
                    int b = (LVLR < 2) ? __float2int_rd(fmaf(FARR[e], SCR, 128.0f)) \
                                       : (int)(f2u_ord(FARR[e]) >> 24);             \
                    uint32_t u = f2u_ord(FARR[e]);                                  \
                    if (b == BSELR && u >= curnext) atomicMin(&s_minu, u);          \
                }                                                                   \
                __syncthreads();                                                    \
                uint32_t m = s_minu;                                                \
                if (m == FULLM) {                                                   \
                    if (t == 0) s_T[R] = u2f_ord(curnext - 1u);                     \
                    __syncthreads(); break;                                         \
                }                                                                   \
                _Pragma("unroll")                                                   \
                for (int e = 0; e < 8; e++)                                         \
                    if (f2u_ord(FARR[e]) == m) atomicAdd(&s_c, 1u);                 \
                __syncthreads();                                                    \
                uint32_t dup = s_c;                                                 \
                if ((int)dup >= rem) {                                              \
                    if (t == 0) s_T[R] = u2f_ord(m);                                \
                    __syncthreads(); break;                                         \
                }                                                                   \
                rem    -= (int)dup;                                                 \
                curnext = m + 1u;                                                   \
                __syncthreads();                                                    \
            }                                                                       \
        }                                                                           \
    }

    ROW_THRESH(0, fa, lvlA, scA, bselA)
    ROW_THRESH(1, fb, lvlB, scB, bselB)
#undef ROW_THRESH

    __syncthreads();
    const float TA = s_T[0], TB = s_T[1];

    // ---- output both rows from registers ----
    float4 oa0, oa1, ob0, ob1;
    oa0.x = (fa[0] <= TA) ? 0.0f : fa[0];
    oa0.y = (fa[1] <= TA) ? 0.0f : fa[1];
    oa0.z = (fa[2] <= TA) ? 0.0f : fa[2];
    oa0.w = (fa[3] <= TA) ? 0.0f : fa[3];
    oa1.x = (fa[4] <= TA) ? 0.0f : fa[4];
    oa1.y = (fa[5] <= TA) ? 0.0f : fa[5];
    oa1.z = (fa[6] <= TA) ? 0.0f : fa[6];
    oa1.w = (fa[7] <= TA) ? 0.0f : fa[7];
    ob0.x = (fb[0] <= TB) ? 0.0f : fb[0];
    ob0.y = (fb[1] <= TB) ? 0.0f : fb[1];
    ob0.z = (fb[2] <= TB) ? 0.0f : fb[2];
    ob0.w = (fb[3] <= TB) ? 0.0f : fb[3];
    ob1.x = (fb[4] <= TB) ? 0.0f : fb[4];
    ob1.y = (fb[5] <= TB) ? 0.0f : fb[5];
    ob1.z = (fb[6] <= TB) ? 0.0f : fb[6];
    ob1.w = (fb[7] <= TB) ? 0.0f : fb[7];
    outA[t]      = oa0;
    outA[t + NT] = oa1;
    outB[t]      = ob0;
    outB[t + NT] = ob1;
}

extern "C" void kernel_launch(void* const* d_in, const int* in_sizes, int n_in,
                              void* d_out, int out_size) {
    const float* in = (const float*)d_in[0];
    float* out = (float*)d_out;
    int pairs = in_sizes[0] / (2 * ROW_N);
    kta_kernel<<<pairs, NT>>>(in, out);
}

// round 13
// speedup vs baseline: 1.7794x; 1.7779x over previous
#include <cuda_runtime.h>
#include <stdint.h>

#define ROW_N 2048
#define K_SEL 1024
#define NT    256
#define CAP   256
#define FULLM 0xFFFFFFFFu

__device__ __forceinline__ uint32_t f2u_ord(float x) {
    uint32_t b = __float_as_uint(x);
    uint32_t m = (uint32_t)(((int32_t)b) >> 31) | 0x80000000u;
    return b ^ m;
}
__device__ __forceinline__ float u2f_ord(uint32_t u) {
    uint32_t m = (uint32_t)(((int32_t)(~u)) >> 31) | 0x80000000u;
    return __uint_as_float(u ^ m);
}
__device__ __forceinline__ int bin_of(float v, int lvl, float scale) {
    return (lvl < 2) ? __float2int_rd(fmaf(v, scale, 128.0f))
                     : (int)(f2u_ord(v) >> 24);
}

__global__ __launch_bounds__(NT, 7) void kta_kernel(const float* __restrict__ in,
                                                    float* __restrict__ out) {
    __shared__ uint32_t s_hist[512];          // two 256-bin histograms
    __shared__ float    s_cand[2][CAP];       // 2 KB candidate buffers
    __shared__ uint32_t s_w[2][8];
    __shared__ uint32_t s_selbin[2], s_selrem[2];
    __shared__ uint32_t s_cnt[2];
    __shared__ float    s_T[2];
    __shared__ uint32_t s_minu, s_c;

    const int t    = threadIdx.x;
    const int lane = t & 31;
    const int wid  = t >> 5;
    const size_t baseA = (size_t)blockIdx.x * (2 * ROW_N);
    const float4* inA  = (const float4*)(in  + baseA);
    const float4* inB  = (const float4*)(in  + baseA + ROW_N);
    float4*       outA = (float4*)(out + baseA);
    float4*       outB = (float4*)(out + baseA + ROW_N);

    bool gotA = false, gotB = false;
    int  lvlA = 0, lvlB = 0;

    // ================= pass 1: histogram levels (values transient) =================
    for (int lvl = 0; lvl < 3; lvl++) {
        const float scale = (lvl == 0) ? 1280.0f : (256.0f / 1.2f);

        s_hist[t] = 0; s_hist[t + 256] = 0;
        if (t == 0) {
            if (!gotA) s_selbin[0] = FULLM;
            if (!gotB) s_selbin[1] = FULLM;
        }
        __syncthreads();

        if (!gotA) {
            float4 a0 = inA[t], a1 = inA[t + NT];
            float v[8] = {a0.x,a0.y,a0.z,a0.w, a1.x,a1.y,a1.z,a1.w};
            uint32_t clo = 0;
#pragma unroll
            for (int e = 0; e < 8; e++) {
                int b = bin_of(v[e], lvl, scale);
                clo += ((uint32_t)b >> 31);
                if ((unsigned)b < 256u) atomicAdd(&s_hist[b], 1u);
            }
            clo = __reduce_add_sync(FULLM, clo);
            if (lane == 0) s_w[0][wid] = clo;
        }
        if (!gotB) {
            float4 b0 = inB[t], b1 = inB[t + NT];
            float v[8] = {b0.x,b0.y,b0.z,b0.w, b1.x,b1.y,b1.z,b1.w};
            uint32_t clo = 0;
#pragma unroll
            for (int e = 0; e < 8; e++) {
                int b = bin_of(v[e], lvl, scale);
                clo += ((uint32_t)b >> 31);
                if ((unsigned)b < 256u) atomicAdd(&s_hist[256 + b], 1u);
            }
            clo = __reduce_add_sync(FULLM, clo);
            if (lane == 0) s_w[1][wid] = clo;
        }
        __syncthreads();

        // warps 0/1: scan their row's 256 bins, locate crossing bin
        if (wid < 2) {
            const int r = wid;
            const bool need = (r == 0) ? !gotA : !gotB;
            if (need) {
                uint32_t x = (lane < 8) ? s_w[r][lane] : 0u;
                const int clo = (int)__reduce_add_sync(FULLM, x);
                const int k2  = K_SEL - clo;

                const uint4* h4 = (const uint4*)(s_hist + r * 256);
                uint4 p = h4[lane * 2], q = h4[lane * 2 + 1];
                uint32_t c[8] = {p.x,p.y,p.z,p.w, q.x,q.y,q.z,q.w};
                uint32_t lt = c[0]+c[1]+c[2]+c[3]+c[4]+c[5]+c[6]+c[7];
                uint32_t inc = lt;
#pragma unroll
                for (int o = 1; o < 32; o <<= 1) {
                    uint32_t v = __shfl_up_sync(FULLM, inc, o);
                    if (lane >= o) inc += v;
                }
                int exc = (int)(inc - lt);
                if (exc < k2 && k2 <= (int)inc) {
                    int run = exc, fbn = -1;
#pragma unroll
                    for (int j = 0; j < 8; j++) {
                        if (fbn < 0 && run < k2 && k2 <= run + (int)c[j]) fbn = j;
                        else if (fbn < 0) run += (int)c[j];
                    }
                    s_selbin[r] = (uint32_t)(lane * 8 + fbn);
                    s_selrem[r] = (uint32_t)(k2 - run);
                }
            }
        }
        __syncthreads();

        bool pA = gotA, pB = gotB;
        gotA = (s_selbin[0] != FULLM);
        gotB = (s_selbin[1] != FULLM);
        if (!pA && gotA) lvlA = lvl;
        if (!pB && gotB) lvlB = lvl;
        if (gotA && gotB) break;
    }

    const int bselA = (int)s_selbin[0], bselB = (int)s_selbin[1];
    const float scA = (lvlA == 0) ? 1280.0f : (256.0f / 1.2f);
    const float scB = (lvlB == 0) ? 1280.0f : (256.0f / 1.2f);

    if (t == 0) { s_cnt[0] = 0; s_cnt[1] = 0; }
    __syncthreads();

    // ================= pass 2: reload (L2-hit), gather, rank, apply =================
    float4 a0 = inA[t], a1 = inA[t + NT], b0 = inB[t], b1 = inB[t + NT];
    float fa[8] = {a0.x,a0.y,a0.z,a0.w, a1.x,a1.y,a1.z,a1.w};
    float fb[8] = {b0.x,b0.y,b0.z,b0.w, b1.x,b1.y,b1.z,b1.w};

    // gather crossing-bin elements (bit-identical bin math vs pass 1)
#pragma unroll
    for (int e = 0; e < 8; e++) {
        if (bin_of(fa[e], lvlA, scA) == bselA) {
            uint32_t pos = atomicAdd(&s_cnt[0], 1u);
            if (pos < CAP) s_cand[0][pos] = fa[e];
        }
    }
#pragma unroll
    for (int e = 0; e < 8; e++) {
        if (bin_of(fb[e], lvlB, scB) == bselB) {
            uint32_t pos = atomicAdd(&s_cnt[1], 1u);
            if (pos < CAP) s_cand[1][pos] = fb[e];
        }
    }
    __syncthreads();

    // per-row threshold (happy path B<=CAP; buffer-free overflow fallback)
#define ROW_THRESH(R, FARR, LVLR, SCR, BSELR)                                       \
    {                                                                               \
        const int B   = (int)s_cnt[R];                                              \
        int       rem = (int)s_selrem[R];                                           \
        if (B <= CAP) {                                                             \
            if (t < B) {                                                            \
                float v = s_cand[R][t];                                             \
                int less = 0, leq = 0;                                              \
                for (int j = 0; j < B; j++) {                                       \
                    float c = s_cand[R][j];                                         \
                    less += (c <  v) ? 1 : 0;                                       \
                    leq  += (c <= v) ? 1 : 0;                                       \
                }                                                                   \
                if (less < rem && rem <= leq) s_T[R] = v;                           \
            }                                                                       \
        } else {                                                                    \
            uint32_t curnext = 0;                                                   \
            while (true) {                                                          \
                if (t == 0) { s_minu = FULLM; s_c = 0; }                            \
                __syncthreads();                                                    \
                _Pragma("unroll")                                                   \
                for (int e = 0; e < 8; e++) {                                       \
                    uint32_t u = f2u_ord(FARR[e]);                                  \
                    if (bin_of(FARR[e], LVLR, SCR) == BSELR && u >= curnext)        \
                        atomicMin(&s_minu, u);                                      \
                }                                                                   \
                __syncthreads();                                                    \
                uint32_t m = s_minu;                                                \
                if (m == FULLM) {                                                   \
                    if (t == 0) s_T[R] = u2f_ord(curnext - 1u);                     \
                    __syncthreads(); break;                                         \
                }                                                                   \
                _Pragma("unroll")                                                   \
                for (int e = 0; e < 8; e++)                                         \
                    if (f2u_ord(FARR[e]) == m) atomicAdd(&s_c, 1u);                 \
                __syncthreads();                                                    \
                uint32_t dup = s_c;                                                 \
                if ((int)dup >= rem) {                                              \
                    if (t == 0) s_T[R] = u2f_ord(m);                                \
                    __syncthreads(); break;                                         \
                }                                                                   \
                rem    -= (int)dup;                                                 \
                curnext = m + 1u;                                                   \
                __syncthreads();                                                    \
            }                                                                       \
        }                                                                           \
    }

    ROW_THRESH(0, fa, lvlA, scA, bselA)
    ROW_THRESH(1, fb, lvlB, scB, bselB)
#undef ROW_THRESH

    __syncthreads();
    const float TA = s_T[0], TB = s_T[1];

    // apply + store (values still live)
    float4 oa0, oa1, ob0, ob1;
    oa0.x = (fa[0] <= TA) ? 0.0f : fa[0];
    oa0.y = (fa[1] <= TA) ? 0.0f : fa[1];
    oa0.z = (fa[2] <= TA) ? 0.0f : fa[2];
    oa0.w = (fa[3] <= TA) ? 0.0f : fa[3];
    oa1.x = (fa[4] <= TA) ? 0.0f : fa[4];
    oa1.y = (fa[5] <= TA) ? 0.0f : fa[5];
    oa1.z = (fa[6] <= TA) ? 0.0f : fa[6];
    oa1.w = (fa[7] <= TA) ? 0.0f : fa[7];
    ob0.x = (fb[0] <= TB) ? 0.0f : fb[0];
    ob0.y = (fb[1] <= TB) ? 0.0f : fb[1];
    ob0.z = (fb[2] <= TB) ? 0.0f : fb[2];
    ob0.w = (fb[3] <= TB) ? 0.0f : fb[3];
    ob1.x = (fb[4] <= TB) ? 0.0f : fb[4];
    ob1.y = (fb[5] <= TB) ? 0.0f : fb[5];
    ob1.z = (fb[6] <= TB) ? 0.0f : fb[6];
    ob1.w = (fb[7] <= TB) ? 0.0f : fb[7];
    outA[t]      = oa0;
    outA[t + NT] = oa1;
    outB[t]      = ob0;
    outB[t + NT] = ob1;
}

extern "C" void kernel_launch(void* const* d_in, const int* in_sizes, int n_in,
                              void* d_out, int out_size) {
    const float* in = (const float*)d_in[0];
    float* out = (float*)d_out;
    int pairs = in_sizes[0] / (2 * ROW_N);
    kta_kernel<<<pairs, NT>>>(in, out);
}